// round 14
// baseline (speedup 1.0000x reference)
#include <cuda_runtime.h>
#include <cuda_fp16.h>
#include <cstdint>

// ---------------------------------------------------------------------------
// Problem constants
// ---------------------------------------------------------------------------
#define BATCH 8
#define CH    512
#define CQ    128                     // channel quads (s8 path)
#define CP    256                     // channel pairs (fp16 path)
#define LEN   8192
#define PADL  8
#define LPAD  8208
#define KTOT  1536                    // 3 taps * 512 ch
#define WELEM (512*512*3)

// convA (IMMA dual-s8) tiling: BM=128, BN=256, 512 thr, warp 64m x 32n
#define NCHUNK 24
#define ASTRQ  20                     // A smem row stride in u32 (16 + 4 pad)
#define BSTRQ  280                    // B smem row stride in u32 (272 + 8 pad)
#define IA_BYTES (128*ASTRQ*4)        // 10240
#define IPLANE   (16*BSTRQ*4)         // 17920 per plane (16 quad-rows x 272)
#define ISTAGE   (IA_BYTES + 2*IPLANE)   // 46080
#define ISMEM    (2*ISTAGE)              // 92160

// convB (HMMA fp16, R11 geometry): BM=128, BN=256, 512 thr, warp 64m x 32n
#define ASTR 72
#define BCOLS 272
#define BSTR 296
#define FA_BYTES (128*ASTR*2)         // 18432
#define FB_BYTES (32*BSTR*4)          // 37888
#define FSTAGE (FA_BYTES + FB_BYTES)  // 56320
#define FSMEM  (2*FSTAGE)             // 112640
#define NB16 (32*(BCOLS/4))           // 2176

// ---------------------------------------------------------------------------
// Scratch (device globals — no allocation allowed)
// ---------------------------------------------------------------------------
__device__ uint32_t g_Xh[(size_t)BATCH*CQ*LPAD];  // act hi-plane: u32 = 4ch s8, [b*CQ+cq][pos]
__device__ uint32_t g_Xl[(size_t)BATCH*CQ*LPAD];  // act lo-plane
__device__ uint32_t g_H2[(size_t)BATCH*CP*LPAD];  // hidden: u32 = {fp16 c0,c1}, [b*CP+cp][pos]
__device__ char     g_Ws[(size_t)6*512*KTOT];     // ternary weights s8 [o][k=tap*512+c]
__device__ __half   g_Wq[(size_t)6*512*KTOT];     // ternary weights fp16 (convB)
__device__ float    g_scales[6];

// ---------------------------------------------------------------------------
// Helpers
// ---------------------------------------------------------------------------
__device__ __forceinline__ uint32_t smem_u32(const void* p) {
    return (uint32_t)__cvta_generic_to_shared(p);
}
__device__ __forceinline__ uint32_t pack2h(float a, float b) {
    return (uint32_t)__half_as_ushort(__float2half_rn(a)) |
           ((uint32_t)__half_as_ushort(__float2half_rn(b)) << 16);
}
__device__ __forceinline__ void cp16(uint32_t dst, const void* src) {
    asm volatile("cp.async.cg.shared.global [%0], [%1], 16;\n" :: "r"(dst), "l"(src));
}
__device__ __forceinline__ void ldmA(uint32_t a[4], uint32_t addr) {
    asm volatile("ldmatrix.sync.aligned.m8n8.x4.shared.b16 {%0,%1,%2,%3}, [%4];\n"
                 : "=r"(a[0]), "=r"(a[1]), "=r"(a[2]), "=r"(a[3]) : "r"(addr));
}
__device__ __forceinline__ void mma16816(float c[4], const uint32_t a[4], const uint32_t b[2]) {
    asm volatile(
        "mma.sync.aligned.m16n8k16.row.col.f32.f16.f16.f32 "
        "{%0,%1,%2,%3}, {%4,%5,%6,%7}, {%8,%9}, {%0,%1,%2,%3};\n"
        : "+f"(c[0]), "+f"(c[1]), "+f"(c[2]), "+f"(c[3])
        : "r"(a[0]), "r"(a[1]), "r"(a[2]), "r"(a[3]), "r"(b[0]), "r"(b[1]));
}
__device__ __forceinline__ void imma16832(int c[4], const uint32_t a[4], const uint32_t b[2]) {
    asm volatile(
        "mma.sync.aligned.m16n8k32.row.col.s32.s8.s8.s32 "
        "{%0,%1,%2,%3}, {%4,%5,%6,%7}, {%8,%9}, {%0,%1,%2,%3};\n"
        : "+r"(c[0]), "+r"(c[1]), "+r"(c[2]), "+r"(c[3])
        : "r"(a[0]), "r"(a[1]), "r"(a[2]), "r"(a[3]), "r"(b[0]), "r"(b[1]));
}
// x ~= a*(h + l/64), h,l in s8
__device__ __forceinline__ void q8(float v, float inva, int& h, int& l) {
    float s = v * inva;
    h = __float2int_rn(s);
    h = max(-127, min(127, h));
    l = __float2int_rn((s - (float)h) * 64.f);
    l = max(-128, min(127, l));
}

// ---------------------------------------------------------------------------
// Weight prep
// ---------------------------------------------------------------------------
__global__ void scales_all_kernel(const float* w0, const float* w1, const float* w2,
                                  const float* w3, const float* w4, const float* w5) {
    const float* ws[6] = {w0, w1, w2, w3, w4, w5};
    const float* w = ws[blockIdx.x];
    __shared__ float red[1024];
    float s = 0.f;
    for (int i = threadIdx.x; i < WELEM; i += 1024) s += fabsf(w[i]);
    red[threadIdx.x] = s;
    __syncthreads();
    for (int o = 512; o; o >>= 1) {
        if (threadIdx.x < o) red[threadIdx.x] += red[threadIdx.x + o];
        __syncthreads();
    }
    if (threadIdx.x == 0) g_scales[blockIdx.x] = red[0] / (float)WELEM + 1e-5f;
}

__global__ void quant_kernel(const float* w0, const float* w1, const float* w2,
                             const float* w3, const float* w4, const float* w5) {
    const float* ws[6] = {w0, w1, w2, w3, w4, w5};
    size_t idx = (size_t)blockIdx.x * 256 + threadIdx.x;
    if (idx >= (size_t)6 * WELEM) return;
    int widx = (int)(idx / WELEM);
    int rem  = (int)(idx % WELEM);
    int o    = rem / 1536;
    int r2   = rem % 1536;
    int tap  = r2 / 512;
    int cc   = r2 % 512;
    float scale = g_scales[widx];
    float v = ws[widx][((size_t)o * 512 + cc) * 3 + tap];
    float q = rintf(v / scale);                   // round-half-even, matches jnp.round
    q = fminf(1.f, fmaxf(-1.f, q));
    size_t dst = (size_t)widx * 512 * KTOT + (size_t)o * KTOT + tap * 512 + cc;
    g_Wq[dst] = __float2half_rn(q);
    g_Ws[dst] = (char)(int)q;
}

// ---------------------------------------------------------------------------
// Split (branch 0): fp32 [c][pos] -> s8 dual-plane quads + copy x -> out.
// Also zeroes g_H2 halos.  grid ((LPAD+255)/256, BATCH*CQ)
// ---------------------------------------------------------------------------
__global__ void split_kernel(const float* __restrict__ src, float* __restrict__ cpy,
                             float inva) {
    int p  = blockIdx.x * 256 + threadIdx.x;
    int b  = blockIdx.y >> 7;
    int cq = blockIdx.y & 127;
    size_t row = (size_t)b * CQ + cq;
    if (blockIdx.x == 0 && threadIdx.x < 16) {
        int j = threadIdx.x;
        int pos = (j < 8) ? j : (LEN + j);        // halo positions
        g_H2[((size_t)b * CP + 2 * cq) * LPAD + pos] = 0u;
        g_H2[((size_t)b * CP + 2 * cq + 1) * LPAD + pos] = 0u;
    }
    if (p >= LPAD) return;
    int l = p - PADL;
    bool in = (l >= 0) && (l < LEN);
    uint32_t hq = 0, lq = 0;
#pragma unroll
    for (int i = 0; i < 4; ++i) {
        float v = 0.f;
        size_t si = ((size_t)(b * CH + 4 * cq + i)) * LEN + l;
        if (in) v = src[si];
        int h, lo; q8(v, inva, h, lo);
        hq |= (uint32_t)(h & 0xFF) << (8 * i);
        lq |= (uint32_t)(lo & 0xFF) << (8 * i);
        if (in) cpy[si] = v;
    }
    g_Xh[row * LPAD + p] = hq;
    g_Xl[row * LPAD + p] = lq;
}

// ---------------------------------------------------------------------------
// convA: dual-s8 IMMA GEMM.  Reads g_Xh/g_Xl, writes g_H2 (fp16 pairs).
// acc = sum (64*W)*h + W*l  ->  val = wscale*(aIn/64)*acc + bias, LeakyReLU.
// grid (LEN/256, CH/128, BATCH), block 512, smem ISMEM
// ---------------------------------------------------------------------------
__global__ __launch_bounds__(512, 1)
void conv_imma(const float* __restrict__ bias, int widx, int dil, float aIn) {
    extern __shared__ char smem[];

    const int lBase = blockIdx.x * 256;
    const int oBase = blockIdx.y * 128;
    const int bIdx  = blockIdx.z;
    const int tid   = threadIdx.x;
    const int lane  = tid & 31;
    const int wid   = tid >> 5;      // 0..15
    const int wm    = wid >> 3;      // 0..1
    const int wn    = wid & 7;       // 0..7
    const int g     = lane >> 2;
    const int tq    = lane & 3;

    const char* Aw = g_Ws + (size_t)widx * 512 * KTOT;

    uint32_t aQ[2], bQ[2];
#pragma unroll
    for (int s = 0; s < 2; ++s) {
        aQ[s] = smem_u32(smem + s * ISTAGE);
        bQ[s] = aQ[s] + IA_BYTES;
    }

    int c[4][4][4];
#pragma unroll
    for (int mi = 0; mi < 4; ++mi)
#pragma unroll
        for (int ni = 0; ni < 4; ++ni)
#pragma unroll
            for (int r = 0; r < 4; ++r) c[mi][ni][r] = 0;

    auto loadStage = [&](int st, int kc) {
        int tap = kc >> 3;
        int cc  = kc & 7;
        // A: 128 rows x 64 s8 -> 512 cp16 (1 per thread)
        {
            int m = tid >> 2, q4 = tid & 3;
            cp16(aQ[st] + (uint32_t)(m * ASTRQ + q4 * 4) * 4,
                 Aw + (size_t)(oBase + m) * KTOT + tap * 512 + cc * 64 + q4 * 16);
        }
        // B: both planes, 16 quad-rows x 272 u32 each -> 2176 cp16
        {
            size_t rbase = ((size_t)(bIdx * CQ + cc * 16)) * LPAD + (PADL + lBase - 8);
            const uint32_t* XH = g_Xh + rbase;
            const uint32_t* XL = g_Xl + rbase;
#pragma unroll
            for (int j = 0; j < 5; ++j) {
                int r = tid + 512 * j;
                if (r < 2176) {
                    int plane = (r >= 1088) ? 1 : 0;
                    int rr = r - plane * 1088;
                    int p = rr / 68, q = rr % 68;
                    const uint32_t* s = (plane ? XL : XH) + (size_t)p * LPAD + q * 4;
                    cp16(bQ[st] + (uint32_t)plane * IPLANE +
                         (uint32_t)(p * BSTRQ + q * 4) * 4, s);
                }
            }
        }
    };

    auto mmaStage = [&](int st, int colOfs) {
        const uint32_t* As = (const uint32_t*)(smem + st * ISTAGE);
        const uint32_t* BH = (const uint32_t*)(smem + st * ISTAGE + IA_BYTES);
        const uint32_t* BL = BH + IPLANE / 4;
#pragma unroll
        for (int s = 0; s < 2; ++s) {             // 2 x k32 per 64-ch chunk
            uint32_t bh[4][2], bl[4][2];
#pragma unroll
            for (int ni = 0; ni < 4; ++ni) {
                int col = colOfs + wn * 32 + ni * 8 + g;
                bh[ni][0] = BH[(s * 8 + tq) * BSTRQ + col];
                bh[ni][1] = BH[(s * 8 + 4 + tq) * BSTRQ + col];
                bl[ni][0] = BL[(s * 8 + tq) * BSTRQ + col];
                bl[ni][1] = BL[(s * 8 + 4 + tq) * BSTRQ + col];
            }
#pragma unroll
            for (int mi = 0; mi < 4; ++mi) {
                int r0 = wm * 64 + mi * 16 + g;
                uint32_t afr[4], a64[4];
                afr[0] = As[r0 * ASTRQ + s * 8 + tq];
                afr[1] = As[(r0 + 8) * ASTRQ + s * 8 + tq];
                afr[2] = As[r0 * ASTRQ + s * 8 + 4 + tq];
                afr[3] = As[(r0 + 8) * ASTRQ + s * 8 + 4 + tq];
#pragma unroll
                for (int i = 0; i < 4; ++i) a64[i] = (afr[i] & 0x03030303u) << 6;
#pragma unroll
                for (int ni = 0; ni < 4; ++ni) {
                    imma16832(c[mi][ni], a64, bh[ni]);   // 64*W * h
                    imma16832(c[mi][ni], afr, bl[ni]);   // W * l
                }
            }
        }
    };

    loadStage(0, 0);
    asm volatile("cp.async.commit_group;\n" ::: "memory");

    for (int kc = 0; kc < NCHUNK; ++kc) {
        asm volatile("cp.async.wait_group 0;\n" ::: "memory");
        __syncthreads();
        if (kc + 1 < NCHUNK) {
            loadStage((kc + 1) & 1, kc + 1);
            asm volatile("cp.async.commit_group;\n" ::: "memory");
        }
        int tap = kc >> 3;
        mmaStage(kc & 1, 8 + (tap - 1) * dil);
    }

    // ---- epilogue: dequant + bias + leaky -> fp16 pairs into g_H2
    const float fscale = g_scales[widx] * aIn * (1.f / 64.f);
#pragma unroll
    for (int mi = 0; mi < 4; ++mi) {
        int o0 = oBase + wm * 64 + mi * 16 + g;
        float bv0 = bias[o0];
        float bv1 = bias[o0 + 8];
#pragma unroll
        for (int ni = 0; ni < 4; ++ni) {
            int l = lBase + wn * 32 + ni * 8 + tq * 2;
            float v0 = (float)c[mi][ni][0] * fscale + bv0;
            float v1 = (float)c[mi][ni][1] * fscale + bv0;
            float v2 = (float)c[mi][ni][2] * fscale + bv1;
            float v3 = (float)c[mi][ni][3] * fscale + bv1;
            v0 = (v0 >= 0.f) ? v0 : 0.1f * v0;
            v1 = (v1 >= 0.f) ? v1 : 0.1f * v1;
            v2 = (v2 >= 0.f) ? v2 : 0.1f * v2;
            v3 = (v3 >= 0.f) ? v3 : 0.1f * v3;
            float p0 = __shfl_xor_sync(0xffffffffu, v0, 4);
            float p1 = __shfl_xor_sync(0xffffffffu, v1, 4);
            float p2 = __shfl_xor_sync(0xffffffffu, v2, 4);
            float p3 = __shfl_xor_sync(0xffffffffu, v3, 4);
            if ((g & 1) == 0) {
                int cp0 = o0 >> 1;
                int cp1 = cp0 + 4;
                size_t r0i = ((size_t)(bIdx * CP + cp0)) * LPAD + PADL + l;
                size_t r1i = ((size_t)(bIdx * CP + cp1)) * LPAD + PADL + l;
                *(uint2*)(&g_H2[r0i]) = make_uint2(pack2h(v0, p0), pack2h(v1, p1));
                *(uint2*)(&g_H2[r1i]) = make_uint2(pack2h(v2, p2), pack2h(v3, p3));
            }
        }
    }
}

// ---------------------------------------------------------------------------
// convB: fp16 HMMA (R11 geometry).  Reads g_H2; epilogue residual -> out;
// if writeNext, quantizes out_new to s8 quads into g_Xh/g_Xl.
// grid (LEN/256, CH/128, BATCH), block 512, smem FSMEM
// ---------------------------------------------------------------------------
__global__ __launch_bounds__(512, 1)
void conv_f16(const float* __restrict__ bias, int widx,
              float* __restrict__ outF, int writeNext, float invaNext) {
    extern __shared__ char smem[];

    const int lBase = blockIdx.x * 256;
    const int oBase = blockIdx.y * 128;
    const int bIdx  = blockIdx.z;
    const int tid   = threadIdx.x;
    const int lane  = tid & 31;
    const int wid   = tid >> 5;
    const int wm    = wid >> 3;
    const int wn    = wid & 7;
    const int g     = lane >> 2;
    const int tq    = lane & 3;

    const __half* Aw = g_Wq + (size_t)widx * 512 * KTOT;

    uint32_t aB[2], bB[2];
    const uint32_t* bP[2];
#pragma unroll
    for (int s = 0; s < 2; ++s) {
        char* stg = smem + s * FSTAGE;
        aB[s] = smem_u32(stg);
        bB[s] = smem_u32(stg + FA_BYTES);
        bP[s] = (const uint32_t*)(stg + FA_BYTES);
    }

    float c[4][4][4];
#pragma unroll
    for (int mi = 0; mi < 4; ++mi)
#pragma unroll
        for (int ni = 0; ni < 4; ++ni)
#pragma unroll
            for (int r = 0; r < 4; ++r) c[mi][ni][r] = 0.f;

    auto loadStage = [&](int st, int kc) {
        {
            int q = tid * 2;
#pragma unroll
            for (int u = 0; u < 2; ++u, ++q) {
                int m = q >> 3, kch = q & 7;
                cp16(aB[st] + (uint32_t)(m * ASTR + kch * 8) * 2,
                     Aw + (size_t)(oBase + m) * KTOT + kc * 64 + kch * 8);
            }
        }
        {
            int cB = (kc & 7) << 5;
            const uint32_t* srcBase =
                g_H2 + ((size_t)(bIdx * CP + cB)) * LPAD + (PADL + lBase - 8);
#pragma unroll
            for (int j = 0; j < 5; ++j) {
                int r = tid + 512 * j;
                if (r < NB16) {
                    int p = r / (BCOLS / 4), q = r % (BCOLS / 4);
                    cp16(bB[st] + (uint32_t)(p * BSTR + q * 4) * 4,
                         srcBase + (size_t)p * LPAD + q * 4);
                }
            }
        }
    };

    auto mmaStage = [&](int st, int colOfs) {
        const uint32_t* Bsl = bP[st];
#pragma unroll
        for (int s = 0; s < 4; ++s) {
            uint32_t afr[4][4];
#pragma unroll
            for (int mi = 0; mi < 4; ++mi) {
                uint32_t addr = aB[st] +
                    (uint32_t)(((wm * 64 + mi * 16 + (lane & 15)) * ASTR) +
                               s * 16 + ((lane >> 4) << 3)) * 2;
                ldmA(afr[mi], addr);
            }
            uint32_t bfr[4][2];
#pragma unroll
            for (int ni = 0; ni < 4; ++ni) {
                int col = colOfs + wn * 32 + ni * 8 + g;
                bfr[ni][0] = Bsl[(s * 8 + tq) * BSTR + col];
                bfr[ni][1] = Bsl[(s * 8 + 4 + tq) * BSTR + col];
            }
#pragma unroll
            for (int mi = 0; mi < 4; ++mi)
#pragma unroll
                for (int ni = 0; ni < 4; ++ni)
                    mma16816(c[mi][ni], afr[mi], bfr[ni]);
        }
    };

    loadStage(0, 0);
    asm volatile("cp.async.commit_group;\n" ::: "memory");

    for (int kc = 0; kc < NCHUNK; ++kc) {
        asm volatile("cp.async.wait_group 0;\n" ::: "memory");
        __syncthreads();
        if (kc + 1 < NCHUNK) {
            loadStage((kc + 1) & 1, kc + 1);
            asm volatile("cp.async.commit_group;\n" ::: "memory");
        }
        int tap = kc >> 3;                        // FIX (R13 bug): dense conv still
        mmaStage(kc & 1, 8 + (tap - 1));          // needs the per-tap shift (dil=1)
    }

    // ---- epilogue
    const float scale = g_scales[widx];
    auto pack_quad = [&](int bv) -> uint32_t {
        uint32_t x = (uint32_t)(bv & 0xFF);
        x |= (__shfl_xor_sync(0xffffffffu, x, 4) & 0xFFu) << 8;
        x = (x & 0xFFFFu) | ((__shfl_xor_sync(0xffffffffu, x, 8) & 0xFFFFu) << 16);
        return x;
    };
#pragma unroll
    for (int mi = 0; mi < 4; ++mi) {
        int o0 = oBase + wm * 64 + mi * 16 + g;
        float bv0 = bias[o0];
        float bv1 = bias[o0 + 8];
#pragma unroll
        for (int ni = 0; ni < 4; ++ni) {
            int l = lBase + wn * 32 + ni * 8 + tq * 2;
            float v0 = c[mi][ni][0] * scale + bv0;
            float v1 = c[mi][ni][1] * scale + bv0;
            float v2 = c[mi][ni][2] * scale + bv1;
            float v3 = c[mi][ni][3] * scale + bv1;
            size_t i0 = ((size_t)(bIdx * CH + o0)) * LEN + l;
            size_t i1 = ((size_t)(bIdx * CH + o0 + 8)) * LEN + l;
            float2 r0 = *(const float2*)(outF + i0);
            float2 r1 = *(const float2*)(outF + i1);
            float n0 = v0 + r0.x, n1 = v1 + r0.y;
            float n2 = v2 + r1.x, n3 = v3 + r1.y;
            *(float2*)(outF + i0) = make_float2(n0, n1);
            *(float2*)(outF + i1) = make_float2(n2, n3);
            if (writeNext) {
                int h0, l0, h1, l1, h2, l2, h3, l3;
                q8(n0, invaNext, h0, l0); q8(n1, invaNext, h1, l1);
                q8(n2, invaNext, h2, l2); q8(n3, invaNext, h3, l3);
                uint32_t H0 = pack_quad(h0), L0 = pack_quad(l0);
                uint32_t H1 = pack_quad(h1), L1 = pack_quad(l1);
                uint32_t H2q = pack_quad(h2), L2q = pack_quad(l2);
                uint32_t H3q = pack_quad(h3), L3q = pack_quad(l3);
                if ((g & 3) == 0) {               // lanes g=0,4 hold full quads
                    size_t r0q = ((size_t)(bIdx * CQ + (o0 >> 2))) * LPAD + PADL + l;
                    size_t r1q = r0q + 2 * (size_t)LPAD;   // channels +8 -> cq+2
                    *(uint2*)(&g_Xh[r0q]) = make_uint2(H0, H1);
                    *(uint2*)(&g_Xl[r0q]) = make_uint2(L0, L1);
                    *(uint2*)(&g_Xh[r1q]) = make_uint2(H2q, H3q);
                    *(uint2*)(&g_Xl[r1q]) = make_uint2(L2q, L3q);
                }
            }
        }
    }
}

// ---------------------------------------------------------------------------
// Launch.  ncu fixed slot = launch index 3 -> convA(branch0) [IMMA].
//   0: scales  1: quant  2: split  3: convA br0  4: convB br0  ...
// ---------------------------------------------------------------------------
extern "C" void kernel_launch(void* const* d_in, const int* in_sizes, int n_in,
                              void* d_out, int out_size) {
    const float* x = (const float*)d_in[0];
    const float* W[6];
    const float* Bv[6];
    for (int i = 0; i < 6; ++i) {
        W[i]  = (const float*)d_in[1 + 2 * i];
        Bv[i] = (const float*)d_in[2 + 2 * i];
    }
    float* out = (float*)d_out;

    cudaFuncSetAttribute(conv_imma,
                         cudaFuncAttributeMaxDynamicSharedMemorySize, ISMEM);
    cudaFuncSetAttribute(conv_f16,
                         cudaFuncAttributeMaxDynamicSharedMemorySize, FSMEM);

    scales_all_kernel<<<6, 1024>>>(W[0], W[1], W[2], W[3], W[4], W[5]);
    {
        size_t total = (size_t)6 * WELEM;
        int blocks = (int)((total + 255) / 256);
        quant_kernel<<<blocks, 256>>>(W[0], W[1], W[2], W[3], W[4], W[5]);
    }

    const dim3 cgrid(LEN / 256, CH / 128, BATCH);
    const dim3 sgrid((LPAD + 255) / 256, BATCH * CQ);
    const int dils[3] = {1, 3, 5};
    const float aIn[3]  = {8.f / 127.f, 16.f / 127.f, 16.f / 127.f};

    split_kernel<<<sgrid, 256>>>(x, out, 127.f / 8.f);

    for (int br = 0; br < 3; ++br) {
        conv_imma<<<cgrid, 512, ISMEM>>>(Bv[2 * br], 2 * br, dils[br], aIn[br]);
        conv_f16<<<cgrid, 512, FSMEM>>>(Bv[2 * br + 1], 2 * br + 1, out,
                                        br < 2 ? 1 : 0, 127.f / 16.f);
    }
}

// round 15
// speedup vs baseline: 2.5008x; 2.5008x over previous
#include <cuda_runtime.h>
#include <cuda_fp16.h>
#include <cstdint>

// ---------------------------------------------------------------------------
// Problem constants
// ---------------------------------------------------------------------------
#define BATCH 8
#define CH    512
#define CP    256                     // channel pairs
#define LEN   8192
#define PADL  8
#define LPAD  (LEN + 2*PADL)          // 8208
#define KTOT  1536                    // 3 taps * 512 ch (single fp16)
#define WELEM (512*512*3)             // 786432 elems per weight tensor

// conv tiling (R11 winner): BM=128, BN=256, 16 warps (512 thr), warp 64m x 32n
#define BM 128
#define BN 256
#define NCHUNK 24
#define NSTG 2
#define ASTR 72                       // A smem row stride (fp16): 64 + 8 pad
#define BCOLS 272                     // B cols per row: [-8, 264) u32 (halo)
#define BSTR 296                      // B smem row stride (u32): ==8 mod 32
#define A_BYTES (128 * ASTR * 2)      // 18432
#define B_BYTES (32 * BSTR * 4)       // 37888
#define STAGE_BYTES (A_BYTES + B_BYTES)          // 56320
#define SMEM_TOTAL (NSTG * STAGE_BYTES)          // 112640
#define NB16 (32 * (BCOLS / 4))       // cp.async.16 per B tile: 2176

// ---------------------------------------------------------------------------
// Scratch (device globals — no allocation allowed)
// Activations: u32 = {fp16 ch(2cp), fp16 ch(2cp+1)} indexed [b*CP+cp][pos]
// ---------------------------------------------------------------------------
__device__ uint32_t g_X2[(size_t)BATCH*CP*LPAD];
__device__ uint32_t g_H2[(size_t)BATCH*CP*LPAD];
__device__ __half   g_Wq[(size_t)6*512*KTOT];   // ternary weights [o][k=tap*512+c]
__device__ float    g_scales[6];
__device__ float    g_partial[6*64];

// ---------------------------------------------------------------------------
// Helpers
// ---------------------------------------------------------------------------
__device__ __forceinline__ uint32_t smem_u32(const void* p) {
    return (uint32_t)__cvta_generic_to_shared(p);
}
__device__ __forceinline__ uint32_t pack2h(float a, float b) {
    return (uint32_t)__half_as_ushort(__float2half_rn(a)) |
           ((uint32_t)__half_as_ushort(__float2half_rn(b)) << 16);
}
__device__ __forceinline__ void cp16(uint32_t dst, const void* src) {
    asm volatile("cp.async.cg.shared.global [%0], [%1], 16;\n" :: "r"(dst), "l"(src));
}
__device__ __forceinline__ void ldmA(uint32_t a[4], uint32_t addr) {
    asm volatile("ldmatrix.sync.aligned.m8n8.x4.shared.b16 {%0,%1,%2,%3}, [%4];\n"
                 : "=r"(a[0]), "=r"(a[1]), "=r"(a[2]), "=r"(a[3]) : "r"(addr));
}
__device__ __forceinline__ void mma16816(float c[4], const uint32_t a[4], const uint32_t b[2]) {
    asm volatile(
        "mma.sync.aligned.m16n8k16.row.col.f32.f16.f16.f32 "
        "{%0,%1,%2,%3}, {%4,%5,%6,%7}, {%8,%9}, {%0,%1,%2,%3};\n"
        : "+f"(c[0]), "+f"(c[1]), "+f"(c[2]), "+f"(c[3])
        : "r"(a[0]), "r"(a[1]), "r"(a[2]), "r"(a[3]), "r"(b[0]), "r"(b[1]));
}

// ---------------------------------------------------------------------------
// Weight prep: absmean scale, two-phase (64x6 partial blocks -> full-chip BW)
// ---------------------------------------------------------------------------
__global__ void scales_part_kernel(const float* w0, const float* w1, const float* w2,
                                   const float* w3, const float* w4, const float* w5) {
    const float* ws[6] = {w0, w1, w2, w3, w4, w5};
    const float* w = ws[blockIdx.y];
    __shared__ float red[256];
    const int chunk = WELEM / 64;                 // 12288
    int base = blockIdx.x * chunk;
    float s = 0.f;
    for (int i = threadIdx.x; i < chunk; i += 256) s += fabsf(w[base + i]);
    red[threadIdx.x] = s;
    __syncthreads();
    for (int o = 128; o; o >>= 1) {
        if (threadIdx.x < o) red[threadIdx.x] += red[threadIdx.x + o];
        __syncthreads();
    }
    if (threadIdx.x == 0) g_partial[blockIdx.y * 64 + blockIdx.x] = red[0];
}

// quant + folded final scale reduction (widx is constant per block: WELEM%256==0)
__global__ void quant_kernel(const float* w0, const float* w1, const float* w2,
                             const float* w3, const float* w4, const float* w5) {
    const float* ws[6] = {w0, w1, w2, w3, w4, w5};
    size_t idx = (size_t)blockIdx.x * 256 + threadIdx.x;
    int widx = (int)(idx / WELEM);
    __shared__ float sScale;
    if (threadIdx.x == 0) {
        float t = 0.f;
        for (int j = 0; j < 64; ++j) t += g_partial[widx * 64 + j];
        float sc = t / (float)WELEM + 1e-5f;
        sScale = sc;
        if (blockIdx.x % 3072 == 0) g_scales[widx] = sc;   // one writer per widx
    }
    __syncthreads();
    if (idx >= (size_t)6 * WELEM) return;
    int rem  = (int)(idx % WELEM);
    int o    = rem / 1536;
    int r2   = rem % 1536;
    int tap  = r2 / 512;
    int cc   = r2 % 512;
    float v = ws[widx][((size_t)o * 512 + cc) * 3 + tap];
    float q = rintf(v / sScale);                  // round-half-even, matches jnp.round
    q = fminf(1.f, fmaxf(-1.f, q));
    g_Wq[(size_t)widx * 512 * KTOT + (size_t)o * KTOT + tap * 512 + cc] = __float2half_rn(q);
}

// ---------------------------------------------------------------------------
// Split (once, branch 0): fp32 [c][pos] -> fp16x2 u32 [cp][pos] + copy x->out.
// Zeroes both halo regions (epilogues write interior only, so they stay 0).
// grid: (ceil(LPAD/256), BATCH*CP)
// ---------------------------------------------------------------------------
__global__ void split_kernel(const float* __restrict__ src, float* __restrict__ cpy) {
    int p  = blockIdx.x * 256 + threadIdx.x;
    int b  = blockIdx.y >> 8;
    int cp = blockIdx.y & 255;
    size_t row = (size_t)b * CP + cp;
    if (blockIdx.x == 0 && threadIdx.x < 16) {
        int j = threadIdx.x;                      // halo: 0..7 and 8200..8207
        g_H2[row * LPAD + (j < 8 ? j : LEN + j)] = 0u;
    }
    if (p >= LPAD) return;
    int l = p - PADL;
    float v0 = 0.f, v1 = 0.f;
    bool in = (l >= 0) && (l < LEN);
    size_t s0 = ((size_t)(b * CH + 2 * cp)) * LEN + l;
    if (in) {
        v0 = src[s0];
        v1 = src[s0 + LEN];
    }
    g_X2[row * LPAD + p] = pack2h(v0, v1);
    if (in) {
        cpy[s0] = v0;
        cpy[s0 + LEN] = v1;
    }
}

// ---------------------------------------------------------------------------
// GEMM conv kernel (R11 geometry).
// RESID=false: reads g_X2; epilogue scale+bias+leaky -> fp16 pairs into g_H2
// RESID=true : reads g_H2; epilogue scale+bias+residual -> fp32 out; if
//              writeNext, also packs out_new into g_X2 for the next branch.
// grid: (LEN/BN, CH/BM, BATCH), block 512, dynamic smem SMEM_TOTAL
// B tile loaded UNSHIFTED with +-8 u32 halo; dilation shift applied at LDS.
// ---------------------------------------------------------------------------
template <bool RESID>
__global__ __launch_bounds__(512, 1)
void conv_kernel(const float* __restrict__ bias, int widx, int dil,
                 float* __restrict__ outF, int writeNext) {
    extern __shared__ char smem[];

    const int lBase = blockIdx.x * BN;
    const int oBase = blockIdx.y * BM;
    const int bIdx  = blockIdx.z;
    const int tid   = threadIdx.x;
    const int lane  = tid & 31;
    const int wid   = tid >> 5;      // 0..15
    const int wm    = wid >> 3;      // 0..1  (64 m-rows each)
    const int wn    = wid & 7;       // 0..7  (32 n-cols each)
    const int g     = lane >> 2;     // 0..7
    const int tq    = lane & 3;      // 0..3

    const __half* Aw = g_Wq + (size_t)widx * 512 * KTOT;
    const uint32_t* __restrict__ Bin = RESID ? g_H2 : g_X2;

    uint32_t  aB[NSTG];
    uint32_t  bB[NSTG];
    const uint32_t* bP[NSTG];
#pragma unroll
    for (int s = 0; s < NSTG; ++s) {
        char* stg = smem + s * STAGE_BYTES;
        aB[s] = smem_u32(stg);
        bB[s] = smem_u32(stg + A_BYTES);
        bP[s] = (const uint32_t*)(stg + A_BYTES);
    }

    float c[4][4][4];
#pragma unroll
    for (int mi = 0; mi < 4; ++mi)
#pragma unroll
        for (int ni = 0; ni < 4; ++ni)
#pragma unroll
            for (int r = 0; r < 4; ++r) c[mi][ni][r] = 0.f;

    auto loadStage = [&](int st, int kc) {
        // ---- A tile: 128 rows x 64 fp16 -> 2 cp16/thread (1024)
        {
            int q = tid * 2;
#pragma unroll
            for (int u = 0; u < 2; ++u, ++q) {
                int m   = q >> 3;                 // 0..127
                int kch = q & 7;                  // 8 fp16 groups
                cp16(aB[st] + (uint32_t)(m * ASTR + kch * 8) * 2,
                     Aw + (size_t)(oBase + m) * KTOT + kc * 64 + kch * 8);
            }
        }
        // ---- B tile: 32 cp-rows x 272 u32 (cols [-8,264)) -> 2176 cp16
        {
            int cB = (kc & 7) << 5;               // 32 channel-pairs per chunk
            const uint32_t* srcBase =
                Bin + ((size_t)(bIdx * CP + cB)) * LPAD + (PADL + lBase - 8);
#pragma unroll
            for (int j = 0; j < 5; ++j) {
                int r = tid + 512 * j;
                if (r < NB16) {
                    int p = r / (BCOLS / 4);      // cp-row 0..31
                    int q = r % (BCOLS / 4);      // 16B group 0..67
                    cp16(bB[st] + (uint32_t)(p * BSTR + q * 4) * 4,
                         srcBase + (size_t)p * LPAD + q * 4);
                }
            }
        }
    };

    auto mmaStage = [&](int st, int colOfs) {
        const uint32_t* Bsl = bP[st];
#pragma unroll
        for (int s = 0; s < 4; ++s) {             // 4 x k16 per 64-k chunk
            uint32_t afr[4][4];
#pragma unroll
            for (int mi = 0; mi < 4; ++mi) {
                uint32_t addr = aB[st] +
                    (uint32_t)(((wm * 64 + mi * 16 + (lane & 15)) * ASTR) +
                               s * 16 + ((lane >> 4) << 3)) * 2;
                ldmA(afr[mi], addr);
            }
            uint32_t bfr[4][2];
#pragma unroll
            for (int ni = 0; ni < 4; ++ni) {
                int col = colOfs + wn * 32 + ni * 8 + g;
                bfr[ni][0] = Bsl[(s * 8 + tq) * BSTR + col];
                bfr[ni][1] = Bsl[(s * 8 + 4 + tq) * BSTR + col];
            }
#pragma unroll
            for (int mi = 0; mi < 4; ++mi)
#pragma unroll
                for (int ni = 0; ni < 4; ++ni)
                    mma16816(c[mi][ni], afr[mi], bfr[ni]);
        }
    };

    // ---- pipeline: 2 stages, 24 chunks, one barrier per chunk
    loadStage(0, 0);
    asm volatile("cp.async.commit_group;\n" ::: "memory");

    for (int kc = 0; kc < NCHUNK; ++kc) {
        asm volatile("cp.async.wait_group 0;\n" ::: "memory");  // stage kc ready
        __syncthreads();                          // all warps done reading stage kc^1
        if (kc + 1 < NCHUNK) {
            loadStage((kc + 1) & 1, kc + 1);
            asm volatile("cp.async.commit_group;\n" ::: "memory");
        }
        int tap = kc >> 3;                        // 8 chunks per tap
        mmaStage(kc & 1, 8 + (tap - 1) * dil);
    }

    // ---- epilogue
    const float scale = g_scales[widx];
#pragma unroll
    for (int mi = 0; mi < 4; ++mi) {
        int o0 = oBase + wm * 64 + mi * 16 + g;
        float bv0 = bias[o0];
        float bv1 = bias[o0 + 8];
#pragma unroll
        for (int ni = 0; ni < 4; ++ni) {
            int l = lBase + wn * 32 + ni * 8 + tq * 2;
            float v0 = c[mi][ni][0] * scale + bv0;
            float v1 = c[mi][ni][1] * scale + bv0;
            float v2 = c[mi][ni][2] * scale + bv1;
            float v3 = c[mi][ni][3] * scale + bv1;
            if (RESID) {
                size_t i0 = ((size_t)(bIdx * CH + o0)) * LEN + l;
                size_t i1 = ((size_t)(bIdx * CH + o0 + 8)) * LEN + l;
                float2 r0 = *(const float2*)(outF + i0);
                float2 r1 = *(const float2*)(outF + i1);
                float n0 = v0 + r0.x, n1 = v1 + r0.y;
                float n2 = v2 + r1.x, n3 = v3 + r1.y;
                *(float2*)(outF + i0) = make_float2(n0, n1);
                *(float2*)(outF + i1) = make_float2(n2, n3);
                if (writeNext) {                  // pack next branch's input
                    float p0 = __shfl_xor_sync(0xffffffffu, n0, 4);
                    float p1 = __shfl_xor_sync(0xffffffffu, n1, 4);
                    float p2 = __shfl_xor_sync(0xffffffffu, n2, 4);
                    float p3 = __shfl_xor_sync(0xffffffffu, n3, 4);
                    if ((g & 1) == 0) {
                        int cp0 = o0 >> 1;        // rows o0,o0+1
                        int cp1 = cp0 + 4;        // rows o0+8,o0+9
                        size_t r0i = ((size_t)(bIdx * CP + cp0)) * LPAD + PADL + l;
                        size_t r1i = ((size_t)(bIdx * CP + cp1)) * LPAD + PADL + l;
                        *(uint2*)(&g_X2[r0i]) = make_uint2(pack2h(n0, p0), pack2h(n1, p1));
                        *(uint2*)(&g_X2[r1i]) = make_uint2(pack2h(n2, p2), pack2h(n3, p3));
                    }
                }
            } else {
                v0 = (v0 >= 0.f) ? v0 : 0.1f * v0;
                v1 = (v1 >= 0.f) ? v1 : 0.1f * v1;
                v2 = (v2 >= 0.f) ? v2 : 0.1f * v2;
                v3 = (v3 >= 0.f) ? v3 : 0.1f * v3;
                float p0 = __shfl_xor_sync(0xffffffffu, v0, 4);
                float p1 = __shfl_xor_sync(0xffffffffu, v1, 4);
                float p2 = __shfl_xor_sync(0xffffffffu, v2, 4);
                float p3 = __shfl_xor_sync(0xffffffffu, v3, 4);
                if ((g & 1) == 0) {               // even channel lanes store pairs
                    int cp0 = o0 >> 1;            // rows o0,o0+1
                    int cp1 = cp0 + 4;            // rows o0+8,o0+9
                    size_t r0i = ((size_t)(bIdx * CP + cp0)) * LPAD + PADL + l;
                    size_t r1i = ((size_t)(bIdx * CP + cp1)) * LPAD + PADL + l;
                    *(uint2*)(&g_H2[r0i]) = make_uint2(pack2h(v0, p0), pack2h(v1, p1));
                    *(uint2*)(&g_H2[r1i]) = make_uint2(pack2h(v2, p2), pack2h(v3, p3));
                }
            }
        }
    }
}

// ---------------------------------------------------------------------------
// Launch.  ncu's fixed profiled slot is launch index 3 -> first conv kernel.
//   0: scales_part  1: quant(+fin)  2: split  3: convA br0  4: convB br0 ...
// ---------------------------------------------------------------------------
extern "C" void kernel_launch(void* const* d_in, const int* in_sizes, int n_in,
                              void* d_out, int out_size) {
    const float* x = (const float*)d_in[0];
    const float* W[6];
    const float* Bv[6];
    for (int i = 0; i < 6; ++i) {
        W[i]  = (const float*)d_in[1 + 2 * i];
        Bv[i] = (const float*)d_in[2 + 2 * i];
    }
    float* out = (float*)d_out;

    // opt-in to >48KB dynamic smem (eager host-side call; idempotent, not captured)
    cudaFuncSetAttribute(conv_kernel<false>,
                         cudaFuncAttributeMaxDynamicSharedMemorySize, SMEM_TOTAL);
    cudaFuncSetAttribute(conv_kernel<true>,
                         cudaFuncAttributeMaxDynamicSharedMemorySize, SMEM_TOTAL);

    // weight prep (2 launches, full-chip bandwidth)
    scales_part_kernel<<<dim3(64, 6), 256>>>(W[0], W[1], W[2], W[3], W[4], W[5]);
    {
        size_t total = (size_t)6 * WELEM;
        int blocks = (int)((total + 255) / 256);
        quant_kernel<<<blocks, 256>>>(W[0], W[1], W[2], W[3], W[4], W[5]);
    }

    const dim3 cgrid(LEN / BN, CH / BM, BATCH);
    const dim3 sgrid((LPAD + 255) / 256, BATCH * CP);
    const int dils[3] = {1, 3, 5};

    // branch 0 input: split x once (also copies x -> out)
    split_kernel<<<sgrid, 256>>>(x, out);

    for (int br = 0; br < 3; ++br) {
        // conv A (dilated) + leaky -> g_H2
        conv_kernel<false><<<cgrid, 512, SMEM_TOTAL>>>(Bv[2 * br], 2 * br, dils[br],
                                                       nullptr, 0);
        // conv B (dense) + bias + residual -> out; packs g_X2 for next branch
        conv_kernel<true><<<cgrid, 512, SMEM_TOTAL>>>(Bv[2 * br + 1], 2 * br + 1, 1,
                                                      out, br < 2 ? 1 : 0);
    }
}